// round 16
// baseline (speedup 1.0000x reference)
#include <cuda_runtime.h>
#include <cuda_fp16.h>
#include <cstdint>

#define NN 50000
#define NE 800000
#define DD 256
#define GG 128
#define FIN 128
#define DNH 512
#define SCAN_BLK 512
#define SCAN_NB ((NN + SCAN_BLK - 1) / SCAN_BLK)   // 98
#define POOL_BLKS 512
#define POOL_CHUNK ((NN + POOL_BLKS - 1) / POOL_BLKS)   // 98
#define ZP_BLKS 256

// ---------------- scratch (static device globals; no allocation) ----------------
__device__ float g_bufA[NN * DD];          // half reused as final fp16 features
__device__ float g_bufB[NN * DD];          // half reused as fp16 T buffer
__device__ float g_dis[NN];
__device__ int   g_indeg[NN];
__device__ int   g_rowstart[NN + 1];
__device__ int   g_cursor[NN];
__device__ int   g_csr[NE];
__device__ int   g_bsums[128];
__device__ float g_Wf[FIN * DD];
__device__ float g_bf[DD];
__device__ float g_bf2[DD];
__device__ float g_sum[DD];
__device__ float g_sq[DD];
__device__ float g_ca[DD];
__device__ float g_cb[DD];
__device__ float g_pooled[GG * DD];
__device__ float g_cnt[GG];
__device__ float g_l1eff[DD * DNH];
__device__ float g_z1[GG * DNH];
__device__ float g_z2[GG * (DNH / 2)];
// fp16 activation buffers
__device__ __align__(256) __half g_a[NN * DD];   // aggregate out
__device__ __align__(256) __half g_x[NN * DD];   // z (conv out)
// fp16 transposed weights: Wf(128*256) + 4 conv (256*256) + 1 tmp (256*256)
#define WOFF_WF   0
#define WOFF_CV(l)  (32768 + (l) * 65536)
#define WOFF_TMP    (32768 + 4 * 65536)
__device__ __align__(256) __half g_wth[655360];

// ---------------- helpers (sm_80+ base ISA, safe on sm_100) ----------------
__device__ __forceinline__ uint32_t smem_u32(const void* p) {
    uint32_t a;
    asm("{ .reg .u64 t; cvta.to.shared.u64 t, %1; cvt.u32.u64 %0, t; }" : "=r"(a) : "l"(p));
    return a;
}
__device__ __forceinline__ void ldsm4(uint32_t* r, uint32_t addr) {
    asm volatile("ldmatrix.sync.aligned.m8n8.x4.shared.b16 {%0,%1,%2,%3}, [%4];"
                 : "=r"(r[0]), "=r"(r[1]), "=r"(r[2]), "=r"(r[3]) : "r"(addr));
}
__device__ __forceinline__ void mma_f16(float* c, const uint32_t* a, const uint32_t* b) {
    asm volatile(
        "mma.sync.aligned.m16n8k16.row.col.f32.f16.f16.f32 "
        "{%0,%1,%2,%3}, {%4,%5,%6,%7}, {%8,%9}, {%0,%1,%2,%3};"
        : "+f"(c[0]), "+f"(c[1]), "+f"(c[2]), "+f"(c[3])
        : "r"(a[0]), "r"(a[1]), "r"(a[2]), "r"(a[3]), "r"(b[0]), "r"(b[1]));
}
__device__ __forceinline__ uint32_t sw64(uint32_t off) {
    return off ^ ((off >> 3) & 0x30);
}
__device__ __forceinline__ void cpa16(uint32_t dst, const void* src, int pb) {
    asm volatile("cp.async.cg.shared.global [%0], [%1], 16, %2;"
                 :: "r"(dst), "l"(src), "r"(pb));
}
#define CP_COMMIT() asm volatile("cp.async.commit_group;" ::: "memory")
#define CP_WAIT(n)  asm volatile("cp.async.wait_group %0;" :: "n"(n) : "memory")

// ---------------- degree / CSR ----------------
__global__ void k_prep() {
    int i = blockIdx.x * blockDim.x + threadIdx.x;
    if (i < NN) g_indeg[i] = 0;
}
__global__ void k_degcount(const int* __restrict__ dst) {
    int e = blockIdx.x * blockDim.x + threadIdx.x;
    if (e < NE) atomicAdd(&g_indeg[dst[e]], 1);
}
__global__ void k_dis() {
    int i = blockIdx.x * blockDim.x + threadIdx.x;
    if (i < NN) g_dis[i] = rsqrtf((float)(g_indeg[i] + 1));
}
__global__ void k_scan_local() {
    __shared__ int s[SCAN_BLK];
    int gid = blockIdx.x * SCAN_BLK + threadIdx.x;
    int v = (gid < NN) ? g_indeg[gid] : 0;
    s[threadIdx.x] = v;
    __syncthreads();
    for (int off = 1; off < SCAN_BLK; off <<= 1) {
        int t = (threadIdx.x >= off) ? s[threadIdx.x - off] : 0;
        __syncthreads();
        s[threadIdx.x] += t;
        __syncthreads();
    }
    if (gid < NN) g_rowstart[gid] = s[threadIdx.x] - v;
    if (threadIdx.x == SCAN_BLK - 1) g_bsums[blockIdx.x] = s[threadIdx.x];
}
__global__ void k_scan_blocks() {
    __shared__ int s[128];
    int v = (threadIdx.x < SCAN_NB) ? g_bsums[threadIdx.x] : 0;
    s[threadIdx.x] = v;
    __syncthreads();
    for (int off = 1; off < 128; off <<= 1) {
        int t = (threadIdx.x >= off) ? s[threadIdx.x - off] : 0;
        __syncthreads();
        s[threadIdx.x] += t;
        __syncthreads();
    }
    if (threadIdx.x < SCAN_NB) g_bsums[threadIdx.x] = s[threadIdx.x] - v;
}
__global__ void k_scan_add() {
    int gid = blockIdx.x * SCAN_BLK + threadIdx.x;
    if (gid < NN) g_rowstart[gid] += g_bsums[blockIdx.x];
}
__global__ void k_cursor() {
    int i = blockIdx.x * blockDim.x + threadIdx.x;
    if (i < NN) g_cursor[i] = g_rowstart[i];
    if (i == 0) g_rowstart[NN] = NE;
}
__global__ void k_fill(const int* __restrict__ src, const int* __restrict__ dst) {
    int e = blockIdx.x * blockDim.x + threadIdx.x;
    if (e < NE) {
        int d = dst[e];
        int p = atomicAdd(&g_cursor[d], 1);
        g_csr[p] = src[e];
    }
}

// ---------------- fused first-layer weight ----------------
__global__ void k_fuse(const float* __restrict__ flW, const float* __restrict__ flb,
                       const float* __restrict__ c1W) {
    int idx = blockIdx.x * blockDim.x + threadIdx.x;
    if (idx < FIN * DD) {
        int i = idx / DD, c = idx % DD;
        float acc = 0.f;
        for (int k = 0; k < DD; k++) acc += flW[i * DD + k] * c1W[k * DD + c];
        g_Wf[idx] = acc;
    } else if (idx < FIN * DD + DD) {
        int c = idx - FIN * DD;
        float acc = 0.f;
        for (int k = 0; k < DD; k++) acc += flb[k] * c1W[k * DD + c];
        g_bf[c] = acc;
    }
}

// ---------------- weight transpose + fp16 (opt. scale rows by g_ca[k]) ----------
template <bool SCALE>
__global__ void k_wsplit(const float* __restrict__ W, int K, int off) {
    int idx = blockIdx.x * blockDim.x + threadIdx.x;
    if (idx >= K * DD) return;
    int n = idx / K, k = idx % K;
    float v = W[k * DD + n];
    if (SCALE) v *= g_ca[k];
    g_wth[off + idx] = __float2half_rn(v);
}

// ---------------- activation fp16 convert (for input x only) ----------------
__global__ void k_split(const float* __restrict__ A, __half* __restrict__ Ah, int total) {
    int idx = blockIdx.x * blockDim.x + threadIdx.x;
    int i4 = idx * 4;
    if (i4 >= total) return;
    float4 v = *(const float4*)(A + i4);
    __half2 ha = __halves2half2(__float2half_rn(v.x), __float2half_rn(v.y));
    __half2 hb = __halves2half2(__float2half_rn(v.z), __float2half_rn(v.w));
    *(uint2*)(Ah + i4) = make_uint2(*reinterpret_cast<uint32_t*>(&ha),
                                    *reinterpret_cast<uint32_t*>(&hb));
}

// ---------------- stats zero (once, before layer 1) ----------------
__global__ void k_zero() {
    g_sum[threadIdx.x] = 0.f;
    g_sq[threadIdx.x] = 0.f;
}

// ---------------- async-pipelined fp16 mma GEMM, 128x128 tile, 2 CTAs/SM --------------------
// C[M,256] = A @ W ; A fp16 [M][K]; W fp16 pre-transposed [256][K]; fp32 accum.
// OUT==0: fp32 C (+bias)(+relu). OUT==2: fp16 Ch (+bias)(+relu).
// STATS: per-column sum/sum2 of post-relu fp32 output -> g_sum/g_sq (pre-zeroed).
// grid (M/128, 2); 8 warps = 4(M) x 2(N); warp tile 32x64.
// K-chunks of 32 (64B rows, SW64); 4-stage cp.async; stage 16KB -> 64KB/CTA.
#define SMS_A 0
#define SMS_B 8192
#define SM_STAGE 16384
#define SM_TOTAL (4 * SM_STAGE)

template <int OUT, bool BIAS, bool RELU, bool STATS>
__global__ void __launch_bounds__(256, 2)
mma_gemm(const __half* __restrict__ A, const __half* __restrict__ Bth,
         const float* __restrict__ bias, float* __restrict__ C,
         __half* __restrict__ Ch, int M, int K) {
    extern __shared__ char smem[];
    uint32_t sbase = smem_u32(smem);
    int tid = threadIdx.x;
    int w = tid >> 5, lane = tid & 31;
    int warp_m = w & 3;
    int warp_n = w >> 2;
    int row0 = blockIdx.x * 128;
    int col0 = blockIdx.y * 128;

    int sub = lane >> 3, r8 = lane & 7;
    uint32_t a_row = (uint32_t)(warp_m * 32 + r8 + (sub & 1) * 8);
    uint32_t a_kb  = (uint32_t)((sub >> 1) * 16);
    uint32_t b_n   = (uint32_t)(warp_n * 64 + (sub >> 1) * 8 + r8);
    uint32_t b_kb  = (uint32_t)((sub & 1) * 16);

    float acc[2][8][4];
#pragma unroll
    for (int mi = 0; mi < 2; mi++)
#pragma unroll
        for (int ni = 0; ni < 8; ni++)
#pragma unroll
            for (int j = 0; j < 4; j++) acc[mi][ni][j] = 0.f;

    auto issue = [&](int cc, int st) {
        int kk = cc << 5;
        uint32_t sb = sbase + st * SM_STAGE;
#pragma unroll
        for (int q = 0; q < 2; q++) {
            int sI = q * 256 + tid;            // 0..511
            int row = sI >> 2, seg = sI & 3;
            uint32_t sw = sw64((uint32_t)((row << 6) | (seg << 4)));
            size_t arow = (size_t)(row0 + row < M ? row0 + row : 0);
            int pb = (row0 + row < M) ? 16 : 0;
            cpa16(sb + SMS_A + sw, A + arow * K + kk + seg * 8, pb);
            cpa16(sb + SMS_B + sw, Bth + (size_t)(col0 + row) * K + kk + seg * 8, 16);
        }
    };

    int nch = K >> 5;   // >= 4 always here
    issue(0, 0);
    CP_COMMIT();
    issue(1, 1);
    CP_COMMIT();
    issue(2, 2);
    CP_COMMIT();
    int st = 0;
    for (int c = 0; c < nch; c++) {
        if (c + 2 < nch) { CP_WAIT(2); }
        else if (c + 1 < nch) { CP_WAIT(1); }
        else { CP_WAIT(0); }
        __syncthreads();
        if (c + 3 < nch) {
            int s3 = st + 3;
            if (s3 >= 4) s3 -= 4;
            issue(c + 3, s3);
            CP_COMMIT();
        }
        uint32_t stb = sbase + st * SM_STAGE;
#pragma unroll
        for (int ks = 0; ks < 2; ks++) {
            uint32_t kofs = (uint32_t)(ks * 32);
            uint32_t af[2][4], bfr[4][4];
#pragma unroll
            for (int mi = 0; mi < 2; mi++) {
                uint32_t off = ((a_row + mi * 16) << 6) + kofs + a_kb;
                ldsm4(af[mi], stb + SMS_A + sw64(off));
            }
#pragma unroll
            for (int p = 0; p < 4; p++) {
                uint32_t off = ((b_n + p * 16) << 6) + kofs + b_kb;
                ldsm4(bfr[p], stb + SMS_B + sw64(off));
            }
#pragma unroll
            for (int mi = 0; mi < 2; mi++)
#pragma unroll
                for (int ni = 0; ni < 8; ni++)
                    mma_f16(acc[mi][ni], af[mi], &bfr[ni >> 1][(ni & 1) * 2]);
        }
        __syncthreads();
        if (++st == 4) st = 0;
    }

    // ---- epilogue ----
    float* ssum = (float*)smem;           // reuse dead stage smem for column stats
    float* ssq  = ((float*)smem) + 128;
    if (STATS) {
        if (tid < 128) { ssum[tid] = 0.f; ssq[tid] = 0.f; }
        __syncthreads();
    }
    int gid = lane >> 2, tig = lane & 3;
    int rb0 = row0 + warp_m * 32 + gid;
#pragma unroll
    for (int ni = 0; ni < 8; ni++) {
        int cc = col0 + warp_n * 64 + ni * 8 + tig * 2;
        float b0 = BIAS ? bias[cc] : 0.f;
        float b1 = BIAS ? bias[cc + 1] : 0.f;
        float s0 = 0.f, q0 = 0.f, s1 = 0.f, q1 = 0.f;
#pragma unroll
        for (int mi = 0; mi < 2; mi++) {
            int rbase = rb0 + mi * 16;
            float v0 = acc[mi][ni][0] + b0, v1 = acc[mi][ni][1] + b1;
            float v2 = acc[mi][ni][2] + b0, v3 = acc[mi][ni][3] + b1;
            if (RELU) {
                v0 = fmaxf(v0, 0.f); v1 = fmaxf(v1, 0.f);
                v2 = fmaxf(v2, 0.f); v3 = fmaxf(v3, 0.f);
            }
            if (STATS) {
                if (rbase < M)     { s0 += v0; q0 = fmaf(v0, v0, q0); s1 += v1; q1 = fmaf(v1, v1, q1); }
                if (rbase + 8 < M) { s0 += v2; q0 = fmaf(v2, v2, q0); s1 += v3; q1 = fmaf(v3, v3, q1); }
            }
            if (OUT == 0) {
                if (rbase < M) *(float2*)(C + (size_t)rbase * 256 + cc) = make_float2(v0, v1);
                if (rbase + 8 < M)
                    *(float2*)(C + (size_t)(rbase + 8) * 256 + cc) = make_float2(v2, v3);
            } else {
#pragma unroll
                for (int half_ = 0; half_ < 2; half_++) {
                    int r = rbase + half_ * 8;
                    if (r >= M) continue;
                    float a0 = half_ ? v2 : v0, a1 = half_ ? v3 : v1;
                    __half2 hp = __halves2half2(__float2half_rn(a0), __float2half_rn(a1));
                    *(uint32_t*)(Ch + (size_t)r * 256 + cc) = *reinterpret_cast<uint32_t*>(&hp);
                }
            }
        }
        if (STATS) {
            int lc = cc - col0;
            atomicAdd(&ssum[lc], s0);
            atomicAdd(&ssq[lc], q0);
            atomicAdd(&ssum[lc + 1], s1);
            atomicAdd(&ssq[lc + 1], q1);
        }
    }
    if (STATS) {
        __syncthreads();
        if (tid < 128) {
            atomicAdd(&g_sum[col0 + tid], ssum[tid]);
            atomicAdd(&g_sq[col0 + tid], ssq[tid]);
        }
    }
}

// ---------------- plain gather aggregation: fp16 in/out, no bias/relu, 4-way unrolled -------
__global__ void k_aggregate(const __half* __restrict__ m, __half* __restrict__ H) {
    int node = blockIdx.x;
    int tid = threadIdx.x;  // 64 threads, 4 channels each
    const uint2* m2 = (const uint2*)m;
    float dn = g_dis[node];
    uint2 miu = m2[(size_t)node * 64 + tid];
    float2 f0 = __half22float2(*reinterpret_cast<__half2*>(&miu.x));
    float2 f1 = __half22float2(*reinterpret_cast<__half2*>(&miu.y));
    float self = dn * dn;
    float4 acc = make_float4(self * f0.x, self * f0.y, self * f1.x, self * f1.y);
    int s = g_rowstart[node], e = g_rowstart[node + 1];
    int i = s;
    for (; i + 4 <= e; i += 4) {
        int s0 = g_csr[i], s1 = g_csr[i + 1], s2 = g_csr[i + 2], s3 = g_csr[i + 3];
        float w0 = dn * __ldg(&g_dis[s0]);
        float w1 = dn * __ldg(&g_dis[s1]);
        float w2 = dn * __ldg(&g_dis[s2]);
        float w3 = dn * __ldg(&g_dis[s3]);
        uint2 u0 = __ldg(&m2[(size_t)s0 * 64 + tid]);
        uint2 u1 = __ldg(&m2[(size_t)s1 * 64 + tid]);
        uint2 u2 = __ldg(&m2[(size_t)s2 * 64 + tid]);
        uint2 u3 = __ldg(&m2[(size_t)s3 * 64 + tid]);
        float2 a0 = __half22float2(*reinterpret_cast<__half2*>(&u0.x));
        float2 a1 = __half22float2(*reinterpret_cast<__half2*>(&u0.y));
        float2 c0 = __half22float2(*reinterpret_cast<__half2*>(&u1.x));
        float2 c1 = __half22float2(*reinterpret_cast<__half2*>(&u1.y));
        float2 d0 = __half22float2(*reinterpret_cast<__half2*>(&u2.x));
        float2 d1 = __half22float2(*reinterpret_cast<__half2*>(&u2.y));
        float2 e0 = __half22float2(*reinterpret_cast<__half2*>(&u3.x));
        float2 e1 = __half22float2(*reinterpret_cast<__half2*>(&u3.y));
        acc.x = fmaf(w0, a0.x, acc.x); acc.y = fmaf(w0, a0.y, acc.y);
        acc.z = fmaf(w0, a1.x, acc.z); acc.w = fmaf(w0, a1.y, acc.w);
        acc.x = fmaf(w1, c0.x, acc.x); acc.y = fmaf(w1, c0.y, acc.y);
        acc.z = fmaf(w1, c1.x, acc.z); acc.w = fmaf(w1, c1.y, acc.w);
        acc.x = fmaf(w2, d0.x, acc.x); acc.y = fmaf(w2, d0.y, acc.y);
        acc.z = fmaf(w2, d1.x, acc.z); acc.w = fmaf(w2, d1.y, acc.w);
        acc.x = fmaf(w3, e0.x, acc.x); acc.y = fmaf(w3, e0.y, acc.y);
        acc.z = fmaf(w3, e1.x, acc.z); acc.w = fmaf(w3, e1.y, acc.w);
    }
    for (; i < e; i++) {
        int src = g_csr[i];
        float w = dn * __ldg(&g_dis[src]);
        uint2 u = __ldg(&m2[(size_t)src * 64 + tid]);
        float2 a0 = __half22float2(*reinterpret_cast<__half2*>(&u.x));
        float2 a1 = __half22float2(*reinterpret_cast<__half2*>(&u.y));
        acc.x = fmaf(w, a0.x, acc.x);
        acc.y = fmaf(w, a0.y, acc.y);
        acc.z = fmaf(w, a1.x, acc.z);
        acc.w = fmaf(w, a1.y, acc.w);
    }
    __half2 hp = __halves2half2(__float2half_rn(acc.x), __float2half_rn(acc.y));
    __half2 hq = __halves2half2(__float2half_rn(acc.z), __float2half_rn(acc.w));
    ((uint2*)H)[(size_t)node * 64 + tid] =
        make_uint2(*reinterpret_cast<uint32_t*>(&hp), *reinterpret_cast<uint32_t*>(&hq));
}

// ---------------- layer-1 z-pass: z = relu(A + bias) + stats ----------------
__global__ void k_zpass(const __half* __restrict__ A, const float* __restrict__ bias,
                        __half* __restrict__ Z) {
    __shared__ float ss[4][64][4];
    __shared__ float sq_[4][64][4];
    int tid = threadIdx.x;
    int rl = tid >> 6, c64 = tid & 63;
    float4 b4 = ((const float4*)bias)[c64];
    float4 ls = make_float4(0.f, 0.f, 0.f, 0.f);
    float4 lq = make_float4(0.f, 0.f, 0.f, 0.f);
    for (int r = blockIdx.x * 4 + rl; r < NN; r += ZP_BLKS * 4) {
        size_t o = (size_t)r * 64 + c64;
        uint2 u = ((const uint2*)A)[o];
        float2 f0 = __half22float2(*reinterpret_cast<__half2*>(&u.x));
        float2 f1 = __half22float2(*reinterpret_cast<__half2*>(&u.y));
        float v0 = fmaxf(f0.x + b4.x, 0.f);
        float v1 = fmaxf(f0.y + b4.y, 0.f);
        float v2 = fmaxf(f1.x + b4.z, 0.f);
        float v3 = fmaxf(f1.y + b4.w, 0.f);
        __half2 hp = __halves2half2(__float2half_rn(v0), __float2half_rn(v1));
        __half2 hq = __halves2half2(__float2half_rn(v2), __float2half_rn(v3));
        ((uint2*)Z)[o] = make_uint2(*reinterpret_cast<uint32_t*>(&hp),
                                    *reinterpret_cast<uint32_t*>(&hq));
        ls.x += v0; ls.y += v1; ls.z += v2; ls.w += v3;
        lq.x = fmaf(v0, v0, lq.x); lq.y = fmaf(v1, v1, lq.y);
        lq.z = fmaf(v2, v2, lq.z); lq.w = fmaf(v3, v3, lq.w);
    }
    ss[rl][c64][0] = ls.x; ss[rl][c64][1] = ls.y; ss[rl][c64][2] = ls.z; ss[rl][c64][3] = ls.w;
    sq_[rl][c64][0] = lq.x; sq_[rl][c64][1] = lq.y; sq_[rl][c64][2] = lq.z; sq_[rl][c64][3] = lq.w;
    __syncthreads();
    if (rl == 0) {
#pragma unroll
        for (int j = 0; j < 4; j++) {
            float s = ss[0][c64][j] + ss[1][c64][j] + ss[2][c64][j] + ss[3][c64][j];
            float q = sq_[0][c64][j] + sq_[1][c64][j] + sq_[2][c64][j] + sq_[3][c64][j];
            atomicAdd(&g_sum[c64 * 4 + j], s);
            atomicAdd(&g_sq[c64 * 4 + j], q);
        }
    }
}

// ---------------- BN finalize: ca/cb + bf2=tb + zero stats (merged) ----------------
__global__ void k_finalize(const float* __restrict__ gamma, const float* __restrict__ beta,
                           const float* __restrict__ tb) {
    int c = threadIdx.x;
    float mu = g_sum[c] * (1.0f / NN);
    float var = g_sq[c] * (1.0f / NN) - mu * mu;
    float inv = rsqrtf(var + 1e-5f);
    g_ca[c] = gamma[c] * inv;
    g_cb[c] = beta[c] - gamma[c] * mu * inv;
    g_bf2[c] = tb[c];
    g_sum[c] = 0.f;
    g_sq[c] = 0.f;
}

// bias' += cb @ W  (parallel over 8 k-slices of 32)
__global__ void k_biasprep(const float* __restrict__ W) {
    int n = threadIdx.x;
    int k0 = blockIdx.x * 32;
    float acc = 0.f;
    for (int k = k0; k < k0 + 32; k++) acc += g_cb[k] * W[k * DD + n];
    atomicAdd(&g_bf2[n], acc);
}

// ---------------- pooling (run-length over sorted batch_index; fp16 input) ----------------
__global__ void k_pool_zero() {
    int i = blockIdx.x * blockDim.x + threadIdx.x;
    if (i < GG * DD) g_pooled[i] = 0.f;
    if (i < GG) g_cnt[i] = 0.f;
}
__global__ void k_pool2(const __half* __restrict__ h, const int* __restrict__ batch) {
    int c = threadIdx.x;
    int s = blockIdx.x * POOL_CHUNK;
    if (s >= NN) return;
    int e = s + POOL_CHUNK;
    if (e > NN) e = NN;
    int g = batch[s];
    float acc = 0.f;
    int cnt = 0;
    for (int r = s; r < e; r++) {
        int gg = __ldg(&batch[r]);
        if (gg != g) {
            atomicAdd(&g_pooled[g * DD + c], acc);
            if (c == 0) atomicAdd(&g_cnt[g], (float)cnt);
            acc = 0.f;
            cnt = 0;
            g = gg;
        }
        acc += __half2float(h[(size_t)r * DD + c]);
        cnt++;
    }
    atomicAdd(&g_pooled[g * DD + c], acc);
    if (c == 0) atomicAdd(&g_cnt[g], (float)cnt);
}
__global__ void k_pool_div() {
    int i = blockIdx.x * blockDim.x + threadIdx.x;
    if (i < GG * DD) {
        int g = i / DD;
        g_pooled[i] /= fmaxf(g_cnt[g], 1.0f);
    }
}

// ---------------- MLP head ----------------
__global__ void k_l1eff(const float* __restrict__ l1W) {
    int idx = blockIdx.x * blockDim.x + threadIdx.x;
    if (idx >= DD * DNH) return;
    int k = idx / DNH, c = idx % DNH;
    g_l1eff[idx] = l1W[k * DNH + c] + l1W[(k + DD) * DNH + c];
}
__global__ void k_mlp(const float* __restrict__ Z, const float* __restrict__ W,
                      const float* __restrict__ b, float* __restrict__ C,
                      int K, int Ncols, int dorelu) {
    __shared__ float sh[DNH];
    int g = blockIdx.x;
    for (int k = threadIdx.x; k < K; k += blockDim.x) sh[k] = Z[(size_t)g * K + k];
    __syncthreads();
    for (int c = threadIdx.x; c < Ncols; c += blockDim.x) {
        float acc = b[c];
        for (int k = 0; k < K; k++) acc += sh[k] * W[k * Ncols + c];
        if (dorelu) acc = fmaxf(acc, 0.f);
        C[(size_t)g * Ncols + c] = acc;
    }
}

// ---------------- host orchestration ----------------
extern "C" void kernel_launch(void* const* d_in, const int* in_sizes, int n_in,
                              void* d_out, int out_size) {
    (void)in_sizes; (void)n_in; (void)out_size;
    const float* x     = (const float*)d_in[0];
    const int*   ei    = (const int*)d_in[1];
    const int*   batch = (const int*)d_in[2];
    const float* fl_W  = (const float*)d_in[3];
    const float* fl_b  = (const float*)d_in[4];
    const float* c1W   = (const float*)d_in[5];
    const float* c1b   = (const float*)d_in[6];
    const float* tr1W  = (const float*)d_in[7];
    const float* tr1b  = (const float*)d_in[8];
    const float* bn1g  = (const float*)d_in[9];
    const float* bn1b  = (const float*)d_in[10];
    const float* convsW = (const float*)d_in[11];
    const float* convsb = (const float*)d_in[12];
    const float* trsW  = (const float*)d_in[13];
    const float* trsb  = (const float*)d_in[14];
    const float* bnsg  = (const float*)d_in[15];
    const float* bnsb  = (const float*)d_in[16];
    const float* l1W   = (const float*)d_in[17];
    const float* l1b   = (const float*)d_in[18];
    const float* l2W   = (const float*)d_in[19];
    const float* l2b   = (const float*)d_in[20];
    const float* l3W   = (const float*)d_in[21];
    const float* l3b   = (const float*)d_in[22];
    float* out = (float*)d_out;

    void* p;
    cudaGetSymbolAddress(&p, g_bufA);   float* bufA  = (float*)p;
    cudaGetSymbolAddress(&p, g_bufB);   float* bufB  = (float*)p;
    cudaGetSymbolAddress(&p, g_Wf);     float* pWf   = (float*)p;
    cudaGetSymbolAddress(&p, g_bf);     float* pbf   = (float*)p;
    cudaGetSymbolAddress(&p, g_bf2);    float* pbf2  = (float*)p;
    cudaGetSymbolAddress(&p, g_pooled); float* pPool = (float*)p;
    cudaGetSymbolAddress(&p, g_l1eff);  float* pL1   = (float*)p;
    cudaGetSymbolAddress(&p, g_z1);     float* pZ1   = (float*)p;
    cudaGetSymbolAddress(&p, g_z2);     float* pZ2   = (float*)p;
    cudaGetSymbolAddress(&p, g_wth);    __half* pWth = (__half*)p;
    cudaGetSymbolAddress(&p, g_a);      __half* pA = (__half*)p;
    cudaGetSymbolAddress(&p, g_x);      __half* pZ = (__half*)p;
    __half* pT  = (__half*)bufB;   // fp16 T buffer
    __half* pHf = (__half*)bufA;   // fp16 final features

    cudaFuncSetAttribute(mma_gemm<2, true,  false, false>, cudaFuncAttributeMaxDynamicSharedMemorySize, SM_TOTAL);
    cudaFuncSetAttribute(mma_gemm<2, true,  true,  false>, cudaFuncAttributeMaxDynamicSharedMemorySize, SM_TOTAL);
    cudaFuncSetAttribute(mma_gemm<2, true,  true,  true >, cudaFuncAttributeMaxDynamicSharedMemorySize, SM_TOTAL);

    const int* src = ei;
    const int* dst = ei + NE;
    const dim3 gg((NN + 127) / 128, 2);   // 391 M-tiles x 2 N-halves

    // ---- launches 1-4: first GEMM at position 4 (ncu capture lands there) ----
    k_split<<<(NN * FIN / 4 + 255) / 256, 256>>>(x, pA, NN * FIN);                   // 1
    k_fuse<<<(FIN * DD + DD + 255) / 256, 256>>>(fl_W, fl_b, c1W);                   // 2
    k_wsplit<false><<<(FIN * DD + 255) / 256, 256>>>(pWf, FIN, WOFF_WF);             // 3
    // T0 = x@Wf + bf -> fp16 (conv1 pre-applied)
    mma_gemm<2, true, false, false><<<gg, 256, SM_TOTAL>>>(pA, pWth + WOFF_WF, pbf,  // 4
                                                           (float*)0, pT, NN, FIN);

    // ---- degrees + CSR ----
    k_prep<<<(NN + 255) / 256, 256>>>();
    k_degcount<<<(NE + 255) / 256, 256>>>(dst);
    k_dis<<<(NN + 255) / 256, 256>>>();
    k_scan_local<<<SCAN_NB, SCAN_BLK>>>();
    k_scan_blocks<<<1, 128>>>();
    k_scan_add<<<SCAN_NB, SCAN_BLK>>>();
    k_cursor<<<(NN + 255) / 256, 256>>>();
    k_fill<<<(NE + 255) / 256, 256>>>(src, dst);

    // ---- conv weight prep + initial stats zero ----
    for (int l = 0; l < 4; l++)
        k_wsplit<false><<<(DD * DD + 255) / 256, 256>>>(convsW + (size_t)l * DD * DD, DD,
                                                        WOFF_CV(l));
    k_zero<<<1, DD>>>();

    // ---- layer 1 (conv pre-fused; z via elementwise pass) ----
    k_aggregate<<<NN, 64>>>(pT, pA);
    k_zpass<<<ZP_BLKS, 256>>>(pA, c1b, pZ);
    k_finalize<<<1, DD>>>(bn1g, bn1b, tr1b);
    k_biasprep<<<8, DD>>>(tr1W);
    k_wsplit<true><<<(DD * DD + 255) / 256, 256>>>(tr1W, DD, WOFF_TMP);
    mma_gemm<2, true, true, false><<<gg, 256, SM_TOTAL>>>(pZ, pWth + WOFF_TMP, pbf2,
                                                          (float*)0, pT, NN, DD);

    // ---- layers 2-5 ----
    for (int l = 1; l < 5; l++) {
        const float* cb_ = convsb + (l - 1) * DD;
        const float* bg  = bnsg + (l - 1) * DD;
        const float* bb  = bnsb + (l - 1) * DD;
        const float* tW  = trsW + (size_t)(l - 1) * DD * DD;
        const float* tb  = trsb + (l - 1) * DD;

        k_aggregate<<<NN, 64>>>(pT, pA);
        // z = relu(agg @ Wc + cb) with fused BN stats
        mma_gemm<2, true, true, true><<<gg, 256, SM_TOTAL>>>(pA, pWth + WOFF_CV(l - 1),
                                                             cb_, (float*)0, pZ, NN, DD);
        k_finalize<<<1, DD>>>(bg, bb, tb);
        k_biasprep<<<8, DD>>>(tW);
        k_wsplit<true><<<(DD * DD + 255) / 256, 256>>>(tW, DD, WOFF_TMP);
        // T = relu(z @ Wtmp + bias')  (layer 5 -> final features fp16)
        __half* dstT = (l < 4) ? pT : pHf;
        mma_gemm<2, true, true, false><<<gg, 256, SM_TOTAL>>>(pZ, pWth + WOFF_TMP, pbf2,
                                                              (float*)0, dstT, NN, DD);
    }

    // global mean pool (run-length, batch sorted; fp16 input)
    k_pool_zero<<<(GG * DD + 255) / 256, 256>>>();
    k_pool2<<<POOL_BLKS, DD>>>(pHf, batch);
    k_pool_div<<<(GG * DD + 255) / 256, 256>>>();

    // MLP head
    k_l1eff<<<(DD * DNH + 255) / 256, 256>>>(l1W);
    k_mlp<<<GG, 512>>>(pPool, pL1, l1b, pZ1, DD, DNH, 1);
    k_mlp<<<GG, 512>>>(pZ1, l2W, l2b, pZ2, DNH, DNH / 2, 1);
    k_mlp<<<GG, 512>>>(pZ2, l3W, l3b, out, DNH / 2, 10, 0);
}

// round 17
// speedup vs baseline: 1.1119x; 1.1119x over previous
#include <cuda_runtime.h>
#include <cuda_fp16.h>
#include <cstdint>

#define NN 50000
#define NE 800000
#define DD 256
#define GG 128
#define FIN 128
#define DNH 512
#define SCAN_BLK 512
#define SCAN_NB ((NN + SCAN_BLK - 1) / SCAN_BLK)   // 98
#define POOL_BLKS 512
#define POOL_CHUNK ((NN + POOL_BLKS - 1) / POOL_BLKS)   // 98

// ---------------- scratch (static device globals; no allocation) ----------------
__device__ float g_bufA[NN * DD];          // half reused as final fp16 features
__device__ float g_bufB[NN * DD];          // half reused as fp16 m buffer
__device__ float g_dis[NN];
__device__ int   g_indeg[NN];
__device__ int   g_rowstart[NN + 1];
__device__ int   g_cursor[NN];
__device__ int   g_csr[NE];
__device__ int   g_bsums[128];
__device__ float g_Wf[FIN * DD];
__device__ float g_bf[DD];
__device__ float g_bf2[DD];
__device__ float g_sum[DD];
__device__ float g_sq[DD];
__device__ float g_ca[DD];
__device__ float g_cb[DD];
__device__ float g_pooled[GG * DD];
__device__ float g_cnt[GG];
__device__ float g_l1eff[DD * DNH];
__device__ float g_z1[GG * DNH];
__device__ float g_z2[GG * (DNH / 2)];
// fp16 activation buffers
__device__ __align__(256) __half g_a[NN * DD];   // aggregate out / GEMM A
__device__ __align__(256) __half g_x[NN * DD];   // transform out
// fp16 transposed weights: Wf(128*256) + 4 conv (256*256) + 1 tmp (256*256)
#define WOFF_WF   0
#define WOFF_CV(l)  (32768 + (l) * 65536)
#define WOFF_TMP    (32768 + 4 * 65536)
__device__ __align__(256) __half g_wth[655360];

// ---------------- helpers (sm_80+ base ISA, safe on sm_100) ----------------
__device__ __forceinline__ uint32_t smem_u32(const void* p) {
    uint32_t a;
    asm("{ .reg .u64 t; cvta.to.shared.u64 t, %1; cvt.u32.u64 %0, t; }" : "=r"(a) : "l"(p));
    return a;
}
__device__ __forceinline__ void ldsm4(uint32_t* r, uint32_t addr) {
    asm volatile("ldmatrix.sync.aligned.m8n8.x4.shared.b16 {%0,%1,%2,%3}, [%4];"
                 : "=r"(r[0]), "=r"(r[1]), "=r"(r[2]), "=r"(r[3]) : "r"(addr));
}
__device__ __forceinline__ void mma_f16(float* c, const uint32_t* a, const uint32_t* b) {
    asm volatile(
        "mma.sync.aligned.m16n8k16.row.col.f32.f16.f16.f32 "
        "{%0,%1,%2,%3}, {%4,%5,%6,%7}, {%8,%9}, {%0,%1,%2,%3};"
        : "+f"(c[0]), "+f"(c[1]), "+f"(c[2]), "+f"(c[3])
        : "r"(a[0]), "r"(a[1]), "r"(a[2]), "r"(a[3]), "r"(b[0]), "r"(b[1]));
}
__device__ __forceinline__ uint32_t sw64(uint32_t off) {
    return off ^ ((off >> 3) & 0x30);
}
__device__ __forceinline__ void cpa16(uint32_t dst, const void* src, int pb) {
    asm volatile("cp.async.cg.shared.global [%0], [%1], 16, %2;"
                 :: "r"(dst), "l"(src), "r"(pb));
}
#define CP_COMMIT() asm volatile("cp.async.commit_group;" ::: "memory")
#define CP_WAIT(n)  asm volatile("cp.async.wait_group %0;" :: "n"(n) : "memory")

// ---------------- degree / CSR ----------------
__global__ void k_prep() {
    int i = blockIdx.x * blockDim.x + threadIdx.x;
    if (i < NN) g_indeg[i] = 0;
}
__global__ void k_degcount(const int* __restrict__ dst) {
    int e = blockIdx.x * blockDim.x + threadIdx.x;
    if (e < NE) atomicAdd(&g_indeg[dst[e]], 1);
}
__global__ void k_dis() {
    int i = blockIdx.x * blockDim.x + threadIdx.x;
    if (i < NN) g_dis[i] = rsqrtf((float)(g_indeg[i] + 1));
}
__global__ void k_scan_local() {
    __shared__ int s[SCAN_BLK];
    int gid = blockIdx.x * SCAN_BLK + threadIdx.x;
    int v = (gid < NN) ? g_indeg[gid] : 0;
    s[threadIdx.x] = v;
    __syncthreads();
    for (int off = 1; off < SCAN_BLK; off <<= 1) {
        int t = (threadIdx.x >= off) ? s[threadIdx.x - off] : 0;
        __syncthreads();
        s[threadIdx.x] += t;
        __syncthreads();
    }
    if (gid < NN) g_rowstart[gid] = s[threadIdx.x] - v;
    if (threadIdx.x == SCAN_BLK - 1) g_bsums[blockIdx.x] = s[threadIdx.x];
}
__global__ void k_scan_blocks() {
    __shared__ int s[128];
    int v = (threadIdx.x < SCAN_NB) ? g_bsums[threadIdx.x] : 0;
    s[threadIdx.x] = v;
    __syncthreads();
    for (int off = 1; off < 128; off <<= 1) {
        int t = (threadIdx.x >= off) ? s[threadIdx.x - off] : 0;
        __syncthreads();
        s[threadIdx.x] += t;
        __syncthreads();
    }
    if (threadIdx.x < SCAN_NB) g_bsums[threadIdx.x] = s[threadIdx.x] - v;
}
__global__ void k_scan_add() {
    int gid = blockIdx.x * SCAN_BLK + threadIdx.x;
    if (gid < NN) g_rowstart[gid] += g_bsums[blockIdx.x];
}
__global__ void k_cursor() {
    int i = blockIdx.x * blockDim.x + threadIdx.x;
    if (i < NN) g_cursor[i] = g_rowstart[i];
    if (i == 0) g_rowstart[NN] = NE;
}
__global__ void k_fill(const int* __restrict__ src, const int* __restrict__ dst) {
    int e = blockIdx.x * blockDim.x + threadIdx.x;
    if (e < NE) {
        int d = dst[e];
        int p = atomicAdd(&g_cursor[d], 1);
        g_csr[p] = src[e];
    }
}

// ---------------- fused first-layer weight ----------------
__global__ void k_fuse(const float* __restrict__ flW, const float* __restrict__ flb,
                       const float* __restrict__ c1W) {
    int idx = blockIdx.x * blockDim.x + threadIdx.x;
    if (idx < FIN * DD) {
        int i = idx / DD, c = idx % DD;
        float acc = 0.f;
        for (int k = 0; k < DD; k++) acc += flW[i * DD + k] * c1W[k * DD + c];
        g_Wf[idx] = acc;
    } else if (idx < FIN * DD + DD) {
        int c = idx - FIN * DD;
        float acc = 0.f;
        for (int k = 0; k < DD; k++) acc += flb[k] * c1W[k * DD + c];
        g_bf[c] = acc;
    }
}

// ---------------- weight transpose + fp16 (opt. scale rows by g_ca[k]) ----------
template <bool SCALE>
__global__ void k_wsplit(const float* __restrict__ W, int K, int off) {
    int idx = blockIdx.x * blockDim.x + threadIdx.x;
    if (idx >= K * DD) return;
    int n = idx / K, k = idx % K;
    float v = W[k * DD + n];
    if (SCALE) v *= g_ca[k];
    g_wth[off + idx] = __float2half_rn(v);
}

// ---------------- activation fp16 convert (for input x only) ----------------
__global__ void k_split(const float* __restrict__ A, __half* __restrict__ Ah, int total) {
    int idx = blockIdx.x * blockDim.x + threadIdx.x;
    int i4 = idx * 4;
    if (i4 >= total) return;
    float4 v = *(const float4*)(A + i4);
    __half2 ha = __halves2half2(__float2half_rn(v.x), __float2half_rn(v.y));
    __half2 hb = __halves2half2(__float2half_rn(v.z), __float2half_rn(v.w));
    *(uint2*)(Ah + i4) = make_uint2(*reinterpret_cast<uint32_t*>(&ha),
                                    *reinterpret_cast<uint32_t*>(&hb));
}

// ---------------- stats zero (once, before layer 1) ----------------
__global__ void k_zero() {
    g_sum[threadIdx.x] = 0.f;
    g_sq[threadIdx.x] = 0.f;
}

// ---------------- async-pipelined fp16 mma GEMM, 128x128 tile, 2 CTAs/SM --------------------
// C[M,256] = A @ W ; A fp16 [M][K]; W fp16 pre-transposed [256][K]; fp32 accum.
// OUT==0: fp32 C (+bias)(+relu). OUT==2: fp16 Ch (+bias)(+relu).
// grid (M/128, 2); 8 warps = 4(M) x 2(N); warp tile 32x64.
// K-chunks of 32 (64B rows, SW64); 4-stage cp.async; stage 16KB -> 64KB/CTA.
#define SMS_A 0
#define SMS_B 8192
#define SM_STAGE 16384
#define SM_TOTAL (4 * SM_STAGE)

template <int OUT, bool BIAS, bool RELU>
__global__ void __launch_bounds__(256, 2)
mma_gemm(const __half* __restrict__ A, const __half* __restrict__ Bth,
         const float* __restrict__ bias, float* __restrict__ C,
         __half* __restrict__ Ch, int M, int K) {
    extern __shared__ char smem[];
    uint32_t sbase = smem_u32(smem);
    int tid = threadIdx.x;
    int w = tid >> 5, lane = tid & 31;
    int warp_m = w & 3;
    int warp_n = w >> 2;
    int row0 = blockIdx.x * 128;
    int col0 = blockIdx.y * 128;

    int sub = lane >> 3, r8 = lane & 7;
    uint32_t a_row = (uint32_t)(warp_m * 32 + r8 + (sub & 1) * 8);
    uint32_t a_kb  = (uint32_t)((sub >> 1) * 16);
    uint32_t b_n   = (uint32_t)(warp_n * 64 + (sub >> 1) * 8 + r8);
    uint32_t b_kb  = (uint32_t)((sub & 1) * 16);

    float acc[2][8][4];
#pragma unroll
    for (int mi = 0; mi < 2; mi++)
#pragma unroll
        for (int ni = 0; ni < 8; ni++)
#pragma unroll
            for (int j = 0; j < 4; j++) acc[mi][ni][j] = 0.f;

    auto issue = [&](int cc, int st) {
        int kk = cc << 5;
        uint32_t sb = sbase + st * SM_STAGE;
#pragma unroll
        for (int q = 0; q < 2; q++) {
            int sI = q * 256 + tid;            // 0..511
            int row = sI >> 2, seg = sI & 3;
            uint32_t sw = sw64((uint32_t)((row << 6) | (seg << 4)));
            size_t arow = (size_t)(row0 + row < M ? row0 + row : 0);
            int pb = (row0 + row < M) ? 16 : 0;
            cpa16(sb + SMS_A + sw, A + arow * K + kk + seg * 8, pb);
            cpa16(sb + SMS_B + sw, Bth + (size_t)(col0 + row) * K + kk + seg * 8, 16);
        }
    };

    int nch = K >> 5;   // >= 4 always here
    issue(0, 0);
    CP_COMMIT();
    issue(1, 1);
    CP_COMMIT();
    issue(2, 2);
    CP_COMMIT();
    int st = 0;
    for (int c = 0; c < nch; c++) {
        if (c + 2 < nch) { CP_WAIT(2); }
        else if (c + 1 < nch) { CP_WAIT(1); }
        else { CP_WAIT(0); }
        __syncthreads();
        if (c + 3 < nch) {
            int s3 = st + 3;
            if (s3 >= 4) s3 -= 4;
            issue(c + 3, s3);
            CP_COMMIT();
        }
        uint32_t stb = sbase + st * SM_STAGE;
#pragma unroll
        for (int ks = 0; ks < 2; ks++) {
            uint32_t kofs = (uint32_t)(ks * 32);
            uint32_t af[2][4], bfr[4][4];
#pragma unroll
            for (int mi = 0; mi < 2; mi++) {
                uint32_t off = ((a_row + mi * 16) << 6) + kofs + a_kb;
                ldsm4(af[mi], stb + SMS_A + sw64(off));
            }
#pragma unroll
            for (int p = 0; p < 4; p++) {
                uint32_t off = ((b_n + p * 16) << 6) + kofs + b_kb;
                ldsm4(bfr[p], stb + SMS_B + sw64(off));
            }
#pragma unroll
            for (int mi = 0; mi < 2; mi++)
#pragma unroll
                for (int ni = 0; ni < 8; ni++)
                    mma_f16(acc[mi][ni], af[mi], &bfr[ni >> 1][(ni & 1) * 2]);
        }
        __syncthreads();
        if (++st == 4) st = 0;
    }

    // ---- epilogue ----
    int gid = lane >> 2, tig = lane & 3;
#pragma unroll
    for (int mi = 0; mi < 2; mi++) {
        int rbase = row0 + warp_m * 32 + mi * 16 + gid;
#pragma unroll
        for (int ni = 0; ni < 8; ni++) {
            int cc = col0 + warp_n * 64 + ni * 8 + tig * 2;
            float b0 = BIAS ? bias[cc] : 0.f;
            float b1 = BIAS ? bias[cc + 1] : 0.f;
            float v0 = acc[mi][ni][0] + b0, v1 = acc[mi][ni][1] + b1;
            float v2 = acc[mi][ni][2] + b0, v3 = acc[mi][ni][3] + b1;
            if (RELU) {
                v0 = fmaxf(v0, 0.f); v1 = fmaxf(v1, 0.f);
                v2 = fmaxf(v2, 0.f); v3 = fmaxf(v3, 0.f);
            }
            if (OUT == 0) {
                if (rbase < M) *(float2*)(C + (size_t)rbase * 256 + cc) = make_float2(v0, v1);
                if (rbase + 8 < M)
                    *(float2*)(C + (size_t)(rbase + 8) * 256 + cc) = make_float2(v2, v3);
            } else {
#pragma unroll
                for (int half_ = 0; half_ < 2; half_++) {
                    int r = rbase + half_ * 8;
                    if (r >= M) continue;
                    float a0 = half_ ? v2 : v0, a1 = half_ ? v3 : v1;
                    __half2 hp = __halves2half2(__float2half_rn(a0), __float2half_rn(a1));
                    *(uint32_t*)(Ch + (size_t)r * 256 + cc) = *reinterpret_cast<uint32_t*>(&hp);
                }
            }
        }
    }
}

// ---------------- gather aggregation: fp16 m in, bias+relu, fp16 out, 8-way unrolled --------
__global__ void k_aggregate(const __half* __restrict__ m, const float* __restrict__ bias,
                            __half* __restrict__ H) {
    int node = blockIdx.x;
    int tid = threadIdx.x;  // 64 threads, 4 channels each
    const uint2* m2 = (const uint2*)m;
    float dn = g_dis[node];
    uint2 miu = m2[(size_t)node * 64 + tid];
    float2 f0 = __half22float2(*reinterpret_cast<__half2*>(&miu.x));
    float2 f1 = __half22float2(*reinterpret_cast<__half2*>(&miu.y));
    float self = dn * dn;
    float4 b4 = ((const float4*)bias)[tid];
    float4 acc;
    acc.x = fmaf(self, f0.x, b4.x);
    acc.y = fmaf(self, f0.y, b4.y);
    acc.z = fmaf(self, f1.x, b4.z);
    acc.w = fmaf(self, f1.y, b4.w);
    int s = g_rowstart[node], e = g_rowstart[node + 1];
    int i = s;
    for (; i + 8 <= e; i += 8) {
        int sx[8];
#pragma unroll
        for (int j = 0; j < 8; j++) sx[j] = g_csr[i + j];
        float wv[8];
#pragma unroll
        for (int j = 0; j < 8; j++) wv[j] = dn * __ldg(&g_dis[sx[j]]);
        uint2 uv[8];
#pragma unroll
        for (int j = 0; j < 8; j++) uv[j] = __ldg(&m2[(size_t)sx[j] * 64 + tid]);
#pragma unroll
        for (int j = 0; j < 8; j++) {
            float2 a0 = __half22float2(*reinterpret_cast<__half2*>(&uv[j].x));
            float2 a1 = __half22float2(*reinterpret_cast<__half2*>(&uv[j].y));
            acc.x = fmaf(wv[j], a0.x, acc.x);
            acc.y = fmaf(wv[j], a0.y, acc.y);
            acc.z = fmaf(wv[j], a1.x, acc.z);
            acc.w = fmaf(wv[j], a1.y, acc.w);
        }
    }
    for (; i < e; i++) {
        int src = g_csr[i];
        float w = dn * __ldg(&g_dis[src]);
        uint2 u = __ldg(&m2[(size_t)src * 64 + tid]);
        float2 a0 = __half22float2(*reinterpret_cast<__half2*>(&u.x));
        float2 a1 = __half22float2(*reinterpret_cast<__half2*>(&u.y));
        acc.x = fmaf(w, a0.x, acc.x);
        acc.y = fmaf(w, a0.y, acc.y);
        acc.z = fmaf(w, a1.x, acc.z);
        acc.w = fmaf(w, a1.y, acc.w);
    }
    acc.x = fmaxf(acc.x, 0.f);
    acc.y = fmaxf(acc.y, 0.f);
    acc.z = fmaxf(acc.z, 0.f);
    acc.w = fmaxf(acc.w, 0.f);
    __half2 hp = __halves2half2(__float2half_rn(acc.x), __float2half_rn(acc.y));
    __half2 hq = __halves2half2(__float2half_rn(acc.z), __float2half_rn(acc.w));
    ((uint2*)H)[(size_t)node * 64 + tid] =
        make_uint2(*reinterpret_cast<uint32_t*>(&hp), *reinterpret_cast<uint32_t*>(&hq));
}

// ---------------- BN stats (from single fp16) ----------------
__global__ void k_stats(const __half* __restrict__ H) {
    float s = 0.f, q = 0.f;
    int c = threadIdx.x;
    for (int r = blockIdx.x; r < NN; r += gridDim.x) {
        float v = __half2float(H[(size_t)r * DD + c]);
        s += v;
        q += v * v;
    }
    atomicAdd(&g_sum[c], s);
    atomicAdd(&g_sq[c], q);
}

// ---------------- BN finalize: ca/cb + bf2=tb + zero stats (merged) ----------------
__global__ void k_finalize(const float* __restrict__ gamma, const float* __restrict__ beta,
                           const float* __restrict__ tb) {
    int c = threadIdx.x;
    float mu = g_sum[c] * (1.0f / NN);
    float var = g_sq[c] * (1.0f / NN) - mu * mu;
    float inv = rsqrtf(var + 1e-5f);
    g_ca[c] = gamma[c] * inv;
    g_cb[c] = beta[c] - gamma[c] * mu * inv;
    g_bf2[c] = tb[c];
    g_sum[c] = 0.f;
    g_sq[c] = 0.f;
}

// bias' += cb @ W  (parallel over 8 k-slices of 32)
__global__ void k_biasprep(const float* __restrict__ W) {
    int n = threadIdx.x;
    int k0 = blockIdx.x * 32;
    float acc = 0.f;
    for (int k = k0; k < k0 + 32; k++) acc += g_cb[k] * W[k * DD + n];
    atomicAdd(&g_bf2[n], acc);
}

// ---------------- pooling (run-length over sorted batch_index; fp16 input) ----------------
__global__ void k_pool_zero() {
    int i = blockIdx.x * blockDim.x + threadIdx.x;
    if (i < GG * DD) g_pooled[i] = 0.f;
    if (i < GG) g_cnt[i] = 0.f;
}
__global__ void k_pool2(const __half* __restrict__ h, const int* __restrict__ batch) {
    int c = threadIdx.x;
    int s = blockIdx.x * POOL_CHUNK;
    if (s >= NN) return;
    int e = s + POOL_CHUNK;
    if (e > NN) e = NN;
    int g = batch[s];
    float acc = 0.f;
    int cnt = 0;
    for (int r = s; r < e; r++) {
        int gg = __ldg(&batch[r]);
        if (gg != g) {
            atomicAdd(&g_pooled[g * DD + c], acc);
            if (c == 0) atomicAdd(&g_cnt[g], (float)cnt);
            acc = 0.f;
            cnt = 0;
            g = gg;
        }
        acc += __half2float(h[(size_t)r * DD + c]);
        cnt++;
    }
    atomicAdd(&g_pooled[g * DD + c], acc);
    if (c == 0) atomicAdd(&g_cnt[g], (float)cnt);
}
__global__ void k_pool_div() {
    int i = blockIdx.x * blockDim.x + threadIdx.x;
    if (i < GG * DD) {
        int g = i / DD;
        g_pooled[i] /= fmaxf(g_cnt[g], 1.0f);
    }
}

// ---------------- MLP head ----------------
__global__ void k_l1eff(const float* __restrict__ l1W) {
    int idx = blockIdx.x * blockDim.x + threadIdx.x;
    if (idx >= DD * DNH) return;
    int k = idx / DNH, c = idx % DNH;
    g_l1eff[idx] = l1W[k * DNH + c] + l1W[(k + DD) * DNH + c];
}
__global__ void k_mlp(const float* __restrict__ Z, const float* __restrict__ W,
                      const float* __restrict__ b, float* __restrict__ C,
                      int K, int Ncols, int dorelu) {
    __shared__ float sh[DNH];
    int g = blockIdx.x;
    for (int k = threadIdx.x; k < K; k += blockDim.x) sh[k] = Z[(size_t)g * K + k];
    __syncthreads();
    for (int c = threadIdx.x; c < Ncols; c += blockDim.x) {
        float acc = b[c];
        for (int k = 0; k < K; k++) acc += sh[k] * W[k * Ncols + c];
        if (dorelu) acc = fmaxf(acc, 0.f);
        C[(size_t)g * Ncols + c] = acc;
    }
}

// ---------------- host orchestration ----------------
extern "C" void kernel_launch(void* const* d_in, const int* in_sizes, int n_in,
                              void* d_out, int out_size) {
    (void)in_sizes; (void)n_in; (void)out_size;
    const float* x     = (const float*)d_in[0];
    const int*   ei    = (const int*)d_in[1];
    const int*   batch = (const int*)d_in[2];
    const float* fl_W  = (const float*)d_in[3];
    const float* fl_b  = (const float*)d_in[4];
    const float* c1W   = (const float*)d_in[5];
    const float* c1b   = (const float*)d_in[6];
    const float* tr1W  = (const float*)d_in[7];
    const float* tr1b  = (const float*)d_in[8];
    const float* bn1g  = (const float*)d_in[9];
    const float* bn1b  = (const float*)d_in[10];
    const float* convsW = (const float*)d_in[11];
    const float* convsb = (const float*)d_in[12];
    const float* trsW  = (const float*)d_in[13];
    const float* trsb  = (const float*)d_in[14];
    const float* bnsg  = (const float*)d_in[15];
    const float* bnsb  = (const float*)d_in[16];
    const float* l1W   = (const float*)d_in[17];
    const float* l1b   = (const float*)d_in[18];
    const float* l2W   = (const float*)d_in[19];
    const float* l2b   = (const float*)d_in[20];
    const float* l3W   = (const float*)d_in[21];
    const float* l3b   = (const float*)d_in[22];
    float* out = (float*)d_out;

    void* p;
    cudaGetSymbolAddress(&p, g_bufA);   float* bufA  = (float*)p;
    cudaGetSymbolAddress(&p, g_bufB);   float* bufB  = (float*)p;
    cudaGetSymbolAddress(&p, g_Wf);     float* pWf   = (float*)p;
    cudaGetSymbolAddress(&p, g_bf);     float* pbf   = (float*)p;
    cudaGetSymbolAddress(&p, g_bf2);    float* pbf2  = (float*)p;
    cudaGetSymbolAddress(&p, g_pooled); float* pPool = (float*)p;
    cudaGetSymbolAddress(&p, g_l1eff);  float* pL1   = (float*)p;
    cudaGetSymbolAddress(&p, g_z1);     float* pZ1   = (float*)p;
    cudaGetSymbolAddress(&p, g_z2);     float* pZ2   = (float*)p;
    cudaGetSymbolAddress(&p, g_wth);    __half* pWth = (__half*)p;
    cudaGetSymbolAddress(&p, g_a);      __half* pA = (__half*)p;
    cudaGetSymbolAddress(&p, g_x);      __half* pX = (__half*)p;
    __half* pMh = (__half*)bufB;   // fp16 m buffer
    __half* pHf = (__half*)bufA;   // fp16 final features

    cudaFuncSetAttribute(mma_gemm<2, true,  false>, cudaFuncAttributeMaxDynamicSharedMemorySize, SM_TOTAL);
    cudaFuncSetAttribute(mma_gemm<2, true,  true >, cudaFuncAttributeMaxDynamicSharedMemorySize, SM_TOTAL);
    cudaFuncSetAttribute(mma_gemm<2, false, false>, cudaFuncAttributeMaxDynamicSharedMemorySize, SM_TOTAL);

    const int* src = ei;
    const int* dst = ei + NE;
    const dim3 gg((NN + 127) / 128, 2);   // 391 M-tiles x 2 N-halves

    // ---- launches 1-4: first GEMM at position 4 (ncu capture lands there) ----
    k_split<<<(NN * FIN / 4 + 255) / 256, 256>>>(x, pA, NN * FIN);                   // 1
    k_fuse<<<(FIN * DD + DD + 255) / 256, 256>>>(fl_W, fl_b, c1W);                   // 2
    k_wsplit<false><<<(FIN * DD + 255) / 256, 256>>>(pWf, FIN, WOFF_WF);             // 3
    // m0 = x@Wf + bf -> fp16
    mma_gemm<2, true, false><<<gg, 256, SM_TOTAL>>>(pA, pWth + WOFF_WF, pbf,         // 4
                                                    (float*)0, pMh, NN, FIN);

    // ---- degrees + CSR ----
    k_prep<<<(NN + 255) / 256, 256>>>();
    k_degcount<<<(NE + 255) / 256, 256>>>(dst);
    k_dis<<<(NN + 255) / 256, 256>>>();
    k_scan_local<<<SCAN_NB, SCAN_BLK>>>();
    k_scan_blocks<<<1, 128>>>();
    k_scan_add<<<SCAN_NB, SCAN_BLK>>>();
    k_cursor<<<(NN + 255) / 256, 256>>>();
    k_fill<<<(NE + 255) / 256, 256>>>(src, dst);

    // ---- conv weight prep + initial stats zero ----
    for (int l = 0; l < 4; l++)
        k_wsplit<false><<<(DD * DD + 255) / 256, 256>>>(convsW + (size_t)l * DD * DD, DD,
                                                        WOFF_CV(l));
    k_zero<<<1, DD>>>();

    for (int l = 0; l < 5; l++) {
        const float* cb_ = (l == 0) ? c1b  : convsb + (l - 1) * DD;
        const float* bg  = (l == 0) ? bn1g : bnsg + (l - 1) * DD;
        const float* bb  = (l == 0) ? bn1b : bnsb + (l - 1) * DD;
        const float* tW  = (l == 0) ? tr1W : trsW + (size_t)(l - 1) * DD * DD;
        const float* tb  = (l == 0) ? tr1b : trsb + (l - 1) * DD;

        // h = relu(gcn) -> fp16 (gather from fp16 m)
        k_aggregate<<<NN, 64>>>(pMh, cb_, pA);
        k_stats<<<512, DD>>>(pA);
        k_finalize<<<1, DD>>>(bg, bb, tb);        // ca/cb + bf2=tb + zero stats
        k_biasprep<<<8, DD>>>(tW);                // bias' += cb@Wt (parallel)
        // fold BN into transform weight (B side): W' = diag(ca)W
        k_wsplit<true><<<(DD * DD + 255) / 256, 256>>>(tW, DD, WOFF_TMP);
        if (l < 4) {
            // h2 = relu(bn(h)@trW + trb) -> fp16
            mma_gemm<2, true, true><<<gg, 256, SM_TOTAL>>>(pA, pWth + WOFF_TMP, pbf2,
                                                           (float*)0, pX, NN, DD);
            // m = h2 @ convs_W[l] -> fp16
            mma_gemm<2, false, false><<<gg, 256, SM_TOTAL>>>(pX, pWth + WOFF_CV(l),
                                                             (const float*)0, (float*)0,
                                                             pMh, NN, DD);
        } else {
            // last layer: fp16 output for pooling
            mma_gemm<2, true, true><<<gg, 256, SM_TOTAL>>>(pA, pWth + WOFF_TMP, pbf2,
                                                           (float*)0, pHf, NN, DD);
        }
    }

    // global mean pool (run-length, batch sorted; fp16 input)
    k_pool_zero<<<(GG * DD + 255) / 256, 256>>>();
    k_pool2<<<POOL_BLKS, DD>>>(pHf, batch);
    k_pool_div<<<(GG * DD + 255) / 256, 256>>>();

    // MLP head
    k_l1eff<<<(DD * DNH + 255) / 256, 256>>>(l1W);
    k_mlp<<<GG, 512>>>(pPool, pL1, l1b, pZ1, DD, DNH, 1);
    k_mlp<<<GG, 512>>>(pZ1, l2W, l2b, pZ2, DNH, DNH / 2, 1);
    k_mlp<<<GG, 512>>>(pZ2, l3W, l3b, out, DNH / 2, 10, 0);
}